// round 9
// baseline (speedup 1.0000x reference)
#include <cuda_runtime.h>
#include <cuda_bf16.h>
#include <cuda_fp16.h>
#include <mma.h>
#include <math.h>

using namespace nvcuda;

#define NMAX 100000
#define EMAX 1600000

// ---------------- static device scratch ------------------------------------
__device__ __align__(16) __nv_bfloat16 g_xh[NMAX * 128];  // X hi (prescaled)
__device__ __align__(16) __nv_bfloat16 g_xl[NMAX * 128];  // X lo (prescaled)
__device__ __align__(16) __half g_bufH[NMAX * 128];       // fp16 GEMM output H
__device__ int   g_col[EMAX];
__device__ int   g_rowptr[NMAX + 1];
__device__ int   g_cursor[NMAX];
__device__ int   g_outdeg[NMAX];
__device__ int   g_indeg[NMAX];
__device__ float g_norm_src[NMAX];
__device__ float g_norm_dst[NMAX];
__device__ int   g_bsums[128];
__device__ int   g_is64;
// W split bf16 hi/lo, transposed to [n][k], bases 0/16384/32768/49152
__device__ __align__(16) __nv_bfloat16 g_wt_hi[57344];
__device__ __align__(16) __nv_bfloat16 g_wt_lo[57344];

// ---------------- preprocessing ---------------------------------------------

__global__ void k_zero(const void* ei, int E, int n,
                       const float* __restrict__ W0, const float* __restrict__ W1,
                       const float* __restrict__ W2, const float* __restrict__ W3)
{
    int nodeBlocks = (n + 255) >> 8;
    int b = blockIdx.x;
    if (b < nodeBlocks) {
        int i = b * 256 + threadIdx.x;
        if (i < n) { g_outdeg[i] = 0; g_indeg[i] = 0; }
        if (b == 0 && threadIdx.x == 0) {
            const unsigned long long* p = (const unsigned long long*)ei;
            int cnt = E < 256 ? E : 256;
            int nz = 0;
            for (int k = 0; k < cnt; k++)
                if ((p[k] >> 32) != 0ULL) nz++;
            g_is64 = (nz == 0) ? 1 : 0;
        }
    } else {
        int id = (b - nodeBlocks) * 256 + threadIdx.x;
        float w; int dst;
        if (id < 49152) {
            int layer = id >> 14;
            int rem = id & 16383;
            int k = rem >> 7, nn = rem & 127;
            const float* W = layer == 0 ? W0 : (layer == 1 ? W1 : W2);
            w = W[rem];
            dst = layer * 16384 + nn * 128 + k;
        } else if (id < 57344) {
            int rem = id - 49152;
            int k = rem >> 6, nn = rem & 63;
            w = W3[rem];
            dst = 49152 + nn * 128 + k;
        } else return;
        __nv_bfloat16 h = __float2bfloat16(w);
        g_wt_hi[dst] = h;
        g_wt_lo[dst] = __float2bfloat16(w - __bfloat162float(h));
    }
}

__device__ __forceinline__ int edge_at(const void* ei, int E, int which, int e) {
    if (g_is64) return (int)((const long long*)ei)[(size_t)which * E + e];
    return ((const int*)ei)[which * E + e];
}

__global__ void k_degree(const void* __restrict__ ei, int E) {
    int e = blockIdx.x * blockDim.x + threadIdx.x;
    if (e < E) {
        atomicAdd(&g_outdeg[edge_at(ei, E, 0, e)], 1);
        atomicAdd(&g_indeg[edge_at(ei, E, 1, e)], 1);
    }
}

__global__ void k_scan_norm(int n) {
    __shared__ int s[2][1024];
    int t = threadIdx.x;
    int i = blockIdx.x * 1024 + t;
    int v = (i < n) ? g_indeg[i] : 0;
    s[0][t] = v;
    __syncthreads();
    int pin = 0;
    #pragma unroll
    for (int off = 1; off < 1024; off <<= 1) {
        int po = pin ^ 1;
        int val = s[pin][t];
        if (t >= off) val += s[pin][t - off];
        s[po][t] = val;
        __syncthreads();
        pin = po;
    }
    int incl = s[pin][t];
    if (i < n) g_rowptr[i] = incl - v;
    if (t == 1023) g_bsums[blockIdx.x] = incl;
    if (i < n) {
        int od = g_outdeg[i];
        g_norm_src[i] = od > 0 ? rsqrtf((float)od) : 0.0f;
        g_norm_dst[i] = v  > 0 ? rsqrtf((float)v)  : 0.0f;
    }
}

__global__ void k_scan_add(int n, int E) {
    __shared__ int s_off;
    int i = blockIdx.x * blockDim.x + threadIdx.x;
    if (threadIdx.x == 0) {
        int b = (blockIdx.x * blockDim.x) >> 10;
        int off = 0;
        for (int k = 0; k < b; k++) off += g_bsums[k];
        s_off = off;
    }
    __syncthreads();
    if (i < n) {
        int r = g_rowptr[i] + s_off;
        g_rowptr[i] = r;
        g_cursor[i] = r;
    }
    if (i == 0) g_rowptr[n] = E;
}

__global__ void k_fill(const void* __restrict__ ei, int E) {
    int e = blockIdx.x * blockDim.x + threadIdx.x;
    if (e < E) {
        int d = edge_at(ei, E, 1, e);
        int pos = atomicAdd(&g_cursor[d], 1);
        g_col[pos] = edge_at(ei, E, 0, e);
    }
}

// ---------------- tensor-core GEMM: H(fp16) = A @ W -------------------------
// CONV=true : A = norm_src * Xext(fp32), split to bf16 hi/lo at staging (layer 0)
// CONV=false: A = g_xh/g_xl (pre-split, prescaled by the previous k_agg)
// 8 warps = 4(M) x 2(N); padded smem stride 40 -> conflict-free LDSM.
// Product = Ah*Bh + Ah*Bl + Al*Bh, fp32 accum.
template <int DOUT, bool CONV>
__global__ void __launch_bounds__(256, 2) k_gemm_mma(
    const float* __restrict__ Xext, int wtBase, int n)
{
    __half* __restrict__ H = g_bufH;

    constexpr int WN = DOUT / 32;
    constexpr int AS = 40;
    __shared__ __align__(16) __nv_bfloat16 Ah[128 * AS];
    __shared__ __align__(16) __nv_bfloat16 Al[128 * AS];
    __shared__ __align__(16) __nv_bfloat16 Bh[DOUT * AS];
    __shared__ __align__(16) __nv_bfloat16 Bl[DOUT * AS];
    __shared__ __align__(16) float Stage[8 * 256];

    int tid  = threadIdx.x;
    int lane = tid & 31;
    int wrp  = tid >> 5;
    int warp_m = wrp >> 1;
    int warp_n = wrp & 1;
    int rows0 = blockIdx.x * 128;

    wmma::fragment<wmma::matrix_a, 16, 16, 16, __nv_bfloat16, wmma::row_major> fa_hi[2], fa_lo[2];
    wmma::fragment<wmma::matrix_b, 16, 16, 16, __nv_bfloat16, wmma::col_major> fb_hi, fb_lo;
    wmma::fragment<wmma::accumulator, 16, 16, 16, float> facc[2][WN];
    #pragma unroll
    for (int fm = 0; fm < 2; fm++)
        #pragma unroll
        for (int fn = 0; fn < WN; fn++) wmma::fill_fragment(facc[fm][fn], 0.0f);

    const __nv_bfloat16* gh = g_wt_hi + wtBase;
    const __nv_bfloat16* gl = g_wt_lo + wtBase;

    for (int kc = 0; kc < 128; kc += 32) {
        if (CONV) {
            // fp32 -> bf16 hi/lo, scaled by norm_src
            #pragma unroll
            for (int u = 0; u < 4; u++) {
                int q = tid + 256 * u;
                int row = q >> 3;
                int kq = q & 7;
                int grow = rows0 + row;
                float4 v = make_float4(0.f, 0.f, 0.f, 0.f);
                float ns = 0.f;
                if (grow < n) {
                    ns = g_norm_src[grow];
                    v = *(const float4*)&Xext[(size_t)grow * 128 + kc + kq * 4];
                }
                float xs[4] = {v.x * ns, v.y * ns, v.z * ns, v.w * ns};
                unsigned hw[4], lw[4];
                #pragma unroll
                for (int j = 0; j < 4; j++) {
                    __nv_bfloat16 h = __float2bfloat16(xs[j]);
                    __nv_bfloat16 l = __float2bfloat16(xs[j] - __bfloat162float(h));
                    hw[j] = (unsigned)__bfloat16_as_ushort(h);
                    lw[j] = (unsigned)__bfloat16_as_ushort(l);
                }
                *(uint2*)&Ah[row * AS + kq * 4] =
                    make_uint2(hw[0] | (hw[1] << 16), hw[2] | (hw[3] << 16));
                *(uint2*)&Al[row * AS + kq * 4] =
                    make_uint2(lw[0] | (lw[1] << 16), lw[2] | (lw[3] << 16));
            }
        } else {
            // pure 16B copies of pre-split A
            #pragma unroll
            for (int u = 0; u < 2; u++) {
                int q = tid + 256 * u;           // 0..511
                int row = q >> 2;
                int kq = q & 3;
                int grow = rows0 + row;
                uint4 vh = make_uint4(0u, 0u, 0u, 0u);
                uint4 vl = vh;
                if (grow < n) {
                    vh = *(const uint4*)&g_xh[(size_t)grow * 128 + kc + kq * 8];
                    vl = *(const uint4*)&g_xl[(size_t)grow * 128 + kc + kq * 8];
                }
                *(uint4*)&Ah[row * AS + kq * 8] = vh;
                *(uint4*)&Al[row * AS + kq * 8] = vl;
            }
        }
        // stage B (4B copies of pre-split bf16)
        for (int q = tid; q < DOUT * 16; q += 256) {
            int rn = q >> 4;
            int k2 = q & 15;
            ((unsigned*)Bh)[rn * (AS / 2) + k2] = ((const unsigned*)gh)[rn * 64 + (kc >> 1) + k2];
            ((unsigned*)Bl)[rn * (AS / 2) + k2] = ((const unsigned*)gl)[rn * 64 + (kc >> 1) + k2];
        }
        __syncthreads();

        #pragma unroll
        for (int kk = 0; kk < 32; kk += 16) {
            #pragma unroll
            for (int fm = 0; fm < 2; fm++) {
                wmma::load_matrix_sync(fa_hi[fm], &Ah[(warp_m * 32 + fm * 16) * AS + kk], AS);
                wmma::load_matrix_sync(fa_lo[fm], &Al[(warp_m * 32 + fm * 16) * AS + kk], AS);
            }
            #pragma unroll
            for (int fn = 0; fn < WN; fn++) {
                int nb = (warp_n * (DOUT / 2) + fn * 16) * AS + kk;
                wmma::load_matrix_sync(fb_hi, &Bh[nb], AS);
                wmma::load_matrix_sync(fb_lo, &Bl[nb], AS);
                #pragma unroll
                for (int fm = 0; fm < 2; fm++) {
                    wmma::mma_sync(facc[fm][fn], fa_hi[fm], fb_hi, facc[fm][fn]);
                    wmma::mma_sync(facc[fm][fn], fa_hi[fm], fb_lo, facc[fm][fn]);
                    wmma::mma_sync(facc[fm][fn], fa_lo[fm], fb_hi, facc[fm][fn]);
                }
            }
        }
        __syncthreads();
    }

    // epilogue: fp32 acc -> fp16 H via per-warp smem staging
    float* st = &Stage[wrp * 256];
    #pragma unroll
    for (int fm = 0; fm < 2; fm++)
        #pragma unroll
        for (int fn = 0; fn < WN; fn++) {
            wmma::store_matrix_sync(st, facc[fm][fn], 16, wmma::mem_row_major);
            __syncwarp();
            int rbase = rows0 + warp_m * 32 + fm * 16;
            int cbase = warp_n * (DOUT / 2) + fn * 16;
            #pragma unroll
            for (int q = lane; q < 128; q += 32) {
                int r = q >> 3, c2 = q & 7;
                int gr = rbase + r;
                if (gr < n) {
                    __half2 hv = __floats2half2_rn(st[r * 16 + c2 * 2],
                                                   st[r * 16 + c2 * 2 + 1]);
                    *(__half2*)&H[(size_t)gr * DOUT + cbase + c2 * 2] = hv;
                }
            }
            __syncwarp();
        }
}

// ---------------- sparse aggregation (one warp per dst, fp16 gather) --------
// SPLIT=true : emit prescaled bf16 hi/lo X for the next GEMM (D=128, ACT)
// SPLIT=false: emit fp32 to outExt (final layer, D=64)
template <int D, bool ACT, bool SPLIT>
__global__ void __launch_bounds__(256) k_agg(
    const float* __restrict__ bias, float* __restrict__ outExt, int n)
{
    const __half* __restrict__ H = g_bufH;

    int gw = (blockIdx.x * blockDim.x + threadIdx.x) >> 5;
    int lane = threadIdx.x & 31;
    if (gw >= n) return;

    int beg = g_rowptr[gw];
    int end = g_rowptr[gw + 1];
    float4 acc = make_float4(0.f, 0.f, 0.f, 0.f);

    for (int e = beg; e < end; e += 32) {
        int m = end - e; if (m > 32) m = 32;
        int idx = (lane < m) ? g_col[e + lane] : 0;
        int j = 0;
        // 2-way unrolled gather for load MLP
        for (; j + 2 <= m; j += 2) {
            int s0 = __shfl_sync(0xffffffffu, idx, j);
            int s1 = __shfl_sync(0xffffffffu, idx, j + 1);
            if (D == 128) {
                float2 r0 = *(const float2*)&H[(size_t)s0 * 128 + lane * 4];
                float2 r1 = *(const float2*)&H[(size_t)s1 * 128 + lane * 4];
                float2 a0 = __half22float2(*(__half2*)&r0.x);
                float2 b0 = __half22float2(*(__half2*)&r0.y);
                float2 a1 = __half22float2(*(__half2*)&r1.x);
                float2 b1 = __half22float2(*(__half2*)&r1.y);
                acc.x += a0.x + a1.x; acc.y += a0.y + a1.y;
                acc.z += b0.x + b1.x; acc.w += b0.y + b1.y;
            } else {
                float2 f0 = __half22float2(*(const __half2*)&H[(size_t)s0 * 64 + lane * 2]);
                float2 f1 = __half22float2(*(const __half2*)&H[(size_t)s1 * 64 + lane * 2]);
                acc.x += f0.x + f1.x; acc.y += f0.y + f1.y;
            }
        }
        if (j < m) {
            int s0 = __shfl_sync(0xffffffffu, idx, j);
            if (D == 128) {
                float2 r0 = *(const float2*)&H[(size_t)s0 * 128 + lane * 4];
                float2 a0 = __half22float2(*(__half2*)&r0.x);
                float2 b0 = __half22float2(*(__half2*)&r0.y);
                acc.x += a0.x; acc.y += a0.y; acc.z += b0.x; acc.w += b0.y;
            } else {
                float2 f0 = __half22float2(*(const __half2*)&H[(size_t)s0 * 64 + lane * 2]);
                acc.x += f0.x; acc.y += f0.y;
            }
        }
    }

    float nd = g_norm_dst[gw];
    if (D == 128) {
        float4 bb = *(const float4*)&bias[lane * 4];
        float4 r;
        r.x = fmaf(acc.x, nd, bb.x);
        r.y = fmaf(acc.y, nd, bb.y);
        r.z = fmaf(acc.z, nd, bb.z);
        r.w = fmaf(acc.w, nd, bb.w);
        if (ACT) { r.x = tanhf(r.x); r.y = tanhf(r.y);
                   r.z = tanhf(r.z); r.w = tanhf(r.w); }
        if (SPLIT) {
            float ps = g_norm_src[gw];
            float vals[4] = {r.x * ps, r.y * ps, r.z * ps, r.w * ps};
            unsigned hw[4], lw[4];
            #pragma unroll
            for (int q = 0; q < 4; q++) {
                __nv_bfloat16 h = __float2bfloat16(vals[q]);
                __nv_bfloat16 l = __float2bfloat16(vals[q] - __bfloat162float(h));
                hw[q] = (unsigned)__bfloat16_as_ushort(h);
                lw[q] = (unsigned)__bfloat16_as_ushort(l);
            }
            *(uint2*)&g_xh[(size_t)gw * 128 + lane * 4] =
                make_uint2(hw[0] | (hw[1] << 16), hw[2] | (hw[3] << 16));
            *(uint2*)&g_xl[(size_t)gw * 128 + lane * 4] =
                make_uint2(lw[0] | (lw[1] << 16), lw[2] | (lw[3] << 16));
        } else {
            *(float4*)&outExt[(size_t)gw * 128 + lane * 4] = r;
        }
    } else {
        float2 bb = *(const float2*)&bias[lane * 2];
        float2 r;
        r.x = fmaf(acc.x, nd, bb.x);
        r.y = fmaf(acc.y, nd, bb.y);
        if (ACT) { r.x = tanhf(r.x); r.y = tanhf(r.y); }
        *(float2*)&outExt[(size_t)gw * 64 + lane * 2] = r;
    }
}

// ---------------- launch ----------------------------------------------------

extern "C" void kernel_launch(void* const* d_in, const int* in_sizes, int n_in,
                              void* d_out, int out_size)
{
    const float* feat = (const float*)d_in[0];
    const void*  ei   = d_in[1];
    const float* W0 = (const float*)d_in[2]; const float* b0 = (const float*)d_in[3];
    const float* W1 = (const float*)d_in[4]; const float* b1 = (const float*)d_in[5];
    const float* W2 = (const float*)d_in[6]; const float* b2 = (const float*)d_in[7];
    const float* W3 = (const float*)d_in[8]; const float* b3 = (const float*)d_in[9];

    int N = in_sizes[0] / 128;
    int E = in_sizes[1] / 2;
    float* out = (float*)d_out;

    int nodeBlocks = (N + 255) / 256;
    int wBlocks = (57344 + 255) / 256;

    k_zero     <<<nodeBlocks + wBlocks, 256>>>(ei, E, N, W0, W1, W2, W3);
    k_degree   <<<(E + 255) / 256, 256>>>(ei, E);
    k_scan_norm<<<(N + 1023) / 1024, 1024>>>(N);

    int gemmGrid = (N + 127) / 128;
    int aggGrid  = (N * 32 + 255) / 256;

    // #4: layer-0 GEMM (profiled launch) — convert path from external feat
    k_gemm_mma<128, true><<<gemmGrid, 256>>>(feat, 0, N);

    // #5,#6: finish CSR (only k_agg needs it)
    k_scan_add<<<(N + 255) / 256, 256>>>(N, E);
    k_fill    <<<(E + 255) / 256, 256>>>(ei, E);

    // remaining layers: agg emits pre-split bf16 X; gemm copies it straight in
    k_agg<128, true, true ><<<aggGrid, 256>>>(b0, nullptr, N);
    k_gemm_mma<128, false><<<gemmGrid, 256>>>(nullptr, 16384, N);
    k_agg<128, true, true ><<<aggGrid, 256>>>(b1, nullptr, N);
    k_gemm_mma<128, false><<<gemmGrid, 256>>>(nullptr, 32768, N);
    k_agg<128, true, true ><<<aggGrid, 256>>>(b2, nullptr, N);
    k_gemm_mma<64, false><<<gemmGrid, 256>>>(nullptr, 49152, N);
    k_agg<64, false, false><<<aggGrid, 256>>>(b3, out, N);
}